// round 1
// baseline (speedup 1.0000x reference)
#include <cuda_runtime.h>
#include <math.h>
#include <stdint.h>

#define BATCH 32
#define TK    8192
#define H     256
#define NROWS (BATCH*TK)     // 262144
#define TM    128            // rows per tile
#define NT    (NROWS/TM)     // 2048 tiles (never straddles a batch: 8192/128=64)
#define GH    128            // g-half (output cols per CTA)
#define KC    32             // k chunk
#define XSTR  36             // Xs row stride (words): (4*lq+lr) distinct mod 32
#define WSTR  136            // Ws row stride (words): (8*lr+lq) distinct mod 32
#define NTHREADS 512

// ---------------- device scratch (static, allocation-free) ----------------
__device__ float g_dec_fea[BATCH*H];
__device__ float g_scores[2][NROWS];
__device__ float g_ct_part[BATCH*32*H];

// ---------------- helpers ----------------
__device__ __forceinline__ unsigned f2tf(float x) {
    unsigned r;
    asm("cvt.rna.tf32.f32 %0, %1;" : "=r"(r) : "f"(x));
    return r;
}
__device__ __forceinline__ float fast_tanh(float x) {
    float r;
    asm("tanh.approx.f32 %0, %1;" : "=f"(r) : "f"(x));
    return r;
}
__device__ __forceinline__ void mma_tf32(float c[4], const unsigned a[4], const unsigned b[2]) {
    asm volatile(
        "mma.sync.aligned.m16n8k8.row.col.f32.tf32.tf32.f32 "
        "{%0,%1,%2,%3}, {%4,%5,%6,%7}, {%8,%9}, {%0,%1,%2,%3};"
        : "+f"(c[0]), "+f"(c[1]), "+f"(c[2]), "+f"(c[3])
        : "r"(a[0]), "r"(a[1]), "r"(a[2]), "r"(a[3]), "r"(b[0]), "r"(b[1]));
}

// ---------------- kernel 1: dec_fea[b,g] = s_t_hat[b,:] @ Wd[g,:] + bd[g] ----------------
__global__ void __launch_bounds__(256)
dec_proj_kernel(const float* __restrict__ s_t_hat,
                const float* __restrict__ Wd,
                const float* __restrict__ bd)
{
    __shared__ float s[512];
    int b = blockIdx.x;
    for (int i = threadIdx.x; i < 512; i += 256) s[i] = s_t_hat[b*512 + i];
    __syncthreads();
    int warp = threadIdx.x >> 5, lane = threadIdx.x & 31;
    for (int g = warp*32; g < warp*32 + 32; g++) {
        const float* w = Wd + (size_t)g*512;
        float acc = 0.f;
        #pragma unroll 4
        for (int j = lane; j < 512; j += 32) acc += s[j]*w[j];
        #pragma unroll
        for (int o = 16; o; o >>= 1) acc += __shfl_xor_sync(0xffffffffu, acc, o);
        if (lane == 0) g_dec_fea[b*H + g] = acc + bd[g];
    }
}

// ---------------- kernel 2: fused projection GEMM + tanh + v-dot -> partial scores ----------------
// grid = 296: gh = blockIdx.x&1 (g-half), persistent over row tiles (stride 148).
// Per CTA: We-half (256k x 128g, tf32) resident in SMEM; 128-row X tiles double-buffered.
__global__ void __launch_bounds__(NTHREADS, 1)
scores_kernel(const float* __restrict__ enc, const float* __restrict__ coverage,
              const float* __restrict__ We, const float* __restrict__ wc,
              const float* __restrict__ v)
{
    extern __shared__ unsigned smem[];
    unsigned* Ws   = smem;                              // 256*WSTR words
    unsigned* Xs   = Ws + 256*WSTR;                     // 2*TM*XSTR words
    float*    sPart= (float*)(Xs + 2*TM*XSTR);          // 4*TM
    float*    decS = sPart + 4*TM;                      // GH
    float*    wcS  = decS + GH;                         // GH
    float*    vS   = wcS + GH;                          // GH

    const int tid    = threadIdx.x;
    const int gh     = blockIdx.x & 1;
    const int tile0  = blockIdx.x >> 1;
    const int tstride= gridDim.x >> 1;

    // Load We half transposed into SMEM as tf32: Ws[k][g'] = We[gh*GH+g'][k]
    for (int idx = tid; idx < GH*(H/4); idx += NTHREADS) {
        int gp = idx >> 6;
        int h4 = (idx & 63) << 2;
        float4 w = *reinterpret_cast<const float4*>(We + (size_t)(gh*GH + gp)*H + h4);
        Ws[(h4+0)*WSTR + gp] = f2tf(w.x);
        Ws[(h4+1)*WSTR + gp] = f2tf(w.y);
        Ws[(h4+2)*WSTR + gp] = f2tf(w.z);
        Ws[(h4+3)*WSTR + gp] = f2tf(w.w);
    }
    if (tid < GH) { wcS[tid] = wc[gh*GH + tid]; vS[tid] = v[gh*GH + tid]; }
    __syncthreads();

    const int warp = tid >> 5, lane = tid & 31;
    const int wr   = warp >> 2, wcl = warp & 3;   // 4 row-warps x 4 col-warps
    const int rbase= wr * 32;
    const int lq   = lane >> 2, lr = lane & 3;

    for (int tile = tile0; tile < NT; tile += tstride) {
        const int row0 = tile * TM;
        const int b    = row0 >> 13;               // /8192
        if (tid < GH) decS[tid] = g_dec_fea[b*H + gh*GH + tid];

        // prefetch chunk 0 into buf 0
        for (int i = tid; i < TM*8; i += NTHREADS) {
            int r = i >> 3, c4 = (i & 7) << 2;
            float4 x = *reinterpret_cast<const float4*>(enc + (size_t)(row0 + r)*H + c4);
            unsigned* xr = Xs + r*XSTR + c4;
            xr[0]=f2tf(x.x); xr[1]=f2tf(x.y); xr[2]=f2tf(x.z); xr[3]=f2tf(x.w);
        }
        __syncthreads();

        float acc[2][4][4];
        #pragma unroll
        for (int m = 0; m < 2; m++)
            #pragma unroll
            for (int n = 0; n < 4; n++)
                #pragma unroll
                for (int q = 0; q < 4; q++) acc[m][n][q] = 0.f;

        for (int kc = 0; kc < 8; kc++) {
            const int cur = kc & 1;
            if (kc < 7) {                           // prefetch next chunk
                const int k0 = (kc + 1) * KC;
                unsigned* dst = Xs + ((kc + 1) & 1) * TM * XSTR;
                for (int i = tid; i < TM*8; i += NTHREADS) {
                    int r = i >> 3, c4 = (i & 7) << 2;
                    float4 x = *reinterpret_cast<const float4*>(enc + (size_t)(row0 + r)*H + k0 + c4);
                    unsigned* xr = dst + r*XSTR + c4;
                    xr[0]=f2tf(x.x); xr[1]=f2tf(x.y); xr[2]=f2tf(x.z); xr[3]=f2tf(x.w);
                }
            }
            const unsigned* Xb = Xs + cur * TM * XSTR;
            #pragma unroll
            for (int k8 = 0; k8 < 4; k8++) {
                const int kk = k8 * 8;
                unsigned a[2][4];
                #pragma unroll
                for (int m = 0; m < 2; m++) {
                    const unsigned* x0 = Xb + (rbase + m*16 + lq)*XSTR + kk + lr;
                    a[m][0] = x0[0];  a[m][2] = x0[4];
                    const unsigned* x1 = x0 + 8*XSTR;
                    a[m][1] = x1[0];  a[m][3] = x1[4];
                }
                const int kabs = kc*KC + kk;
                unsigned bf[4][2];
                #pragma unroll
                for (int n = 0; n < 4; n++) {
                    const int gp = wcl*32 + n*8 + lq;
                    bf[n][0] = Ws[(kabs + lr)*WSTR + gp];
                    bf[n][1] = Ws[(kabs + 4 + lr)*WSTR + gp];
                }
                #pragma unroll
                for (int m = 0; m < 2; m++)
                    #pragma unroll
                    for (int n = 0; n < 4; n++)
                        mma_tf32(acc[m][n], a[m], bf[n]);
            }
            __syncthreads();
        }

        // epilogue: score_partial[r] = sum_g v[g]*tanh(feat + dec + cov*wc)
        float rowsum[4] = {0.f, 0.f, 0.f, 0.f};
        #pragma unroll
        for (int m = 0; m < 2; m++) {
            const int rA = rbase + m*16 + lq;
            const float covA = coverage[row0 + rA];
            const float covB = coverage[row0 + rA + 8];
            #pragma unroll
            for (int n = 0; n < 4; n++) {
                const int g0 = wcl*32 + n*8 + lr*2;
                const float wc0 = wcS[g0], wc1 = wcS[g0+1];
                const float de0 = decS[g0], de1 = decS[g0+1];
                const float v0  = vS[g0],  v1  = vS[g0+1];
                rowsum[m*2]   += v0*fast_tanh(acc[m][n][0] + de0 + covA*wc0)
                               + v1*fast_tanh(acc[m][n][1] + de1 + covA*wc1);
                rowsum[m*2+1] += v0*fast_tanh(acc[m][n][2] + de0 + covB*wc0)
                               + v1*fast_tanh(acc[m][n][3] + de1 + covB*wc1);
            }
        }
        #pragma unroll
        for (int o = 1; o < 4; o <<= 1)
            #pragma unroll
            for (int q = 0; q < 4; q++)
                rowsum[q] += __shfl_xor_sync(0xffffffffu, rowsum[q], o);
        if (lr == 0) {
            #pragma unroll
            for (int m = 0; m < 2; m++) {
                sPart[wcl*TM + rbase + m*16 + lq]     = rowsum[m*2];
                sPart[wcl*TM + rbase + m*16 + 8 + lq] = rowsum[m*2+1];
            }
        }
        __syncthreads();
        if (tid < TM) {   // fixed-order cross-warp combine (deterministic)
            float s = sPart[tid] + sPart[TM+tid] + sPart[2*TM+tid] + sPart[3*TM+tid];
            g_scores[gh][row0 + tid] = s;
        }
        __syncthreads();
    }
}

// ---------------- kernel 3: softmax + mask renorm + new_cov ----------------
__global__ void __launch_bounds__(1024)
softmax_kernel(const float* __restrict__ mask, const float* __restrict__ coverage,
               float* __restrict__ out)
{
    __shared__ float sc[TK];    // 32 KB
    __shared__ float red[32];
    const int b = blockIdx.x, tid = threadIdx.x;
    const int lane = tid & 31, warp = tid >> 5;
    const size_t boff = (size_t)b * TK;

    float lmax = -3.4e38f;
    for (int i = tid; i < TK; i += 1024) {
        float s = g_scores[0][boff + i] + g_scores[1][boff + i];
        sc[i] = s;
        lmax = fmaxf(lmax, s);
    }
    #pragma unroll
    for (int o = 16; o; o >>= 1) lmax = fmaxf(lmax, __shfl_xor_sync(~0u, lmax, o));
    if (lane == 0) red[warp] = lmax;
    __syncthreads();
    float M = red[lane];
    #pragma unroll
    for (int o = 16; o; o >>= 1) M = fmaxf(M, __shfl_xor_sync(~0u, M, o));
    __syncthreads();

    float lsum = 0.f;
    for (int i = tid; i < TK; i += 1024) {
        float e = expf(sc[i] - M);
        sc[i] = e;
        lsum += e;
    }
    #pragma unroll
    for (int o = 16; o; o >>= 1) lsum += __shfl_xor_sync(~0u, lsum, o);
    if (lane == 0) red[warp] = lsum;
    __syncthreads();
    float S = red[lane];
    #pragma unroll
    for (int o = 16; o; o >>= 1) S += __shfl_xor_sync(~0u, S, o);
    __syncthreads();

    const float invS = 1.f / S;
    float lsum2 = 0.f;
    for (int i = tid; i < TK; i += 1024) {
        float a = sc[i] * invS * mask[boff + i];
        sc[i] = a;
        lsum2 += a;
    }
    #pragma unroll
    for (int o = 16; o; o >>= 1) lsum2 += __shfl_xor_sync(~0u, lsum2, o);
    if (lane == 0) red[warp] = lsum2;
    __syncthreads();
    float S2 = red[lane];
    #pragma unroll
    for (int o = 16; o; o >>= 1) S2 += __shfl_xor_sync(~0u, S2, o);

    const float inv2 = 1.f / S2;
    float* attn_out = out + BATCH*H;
    float* ncov_out = attn_out + (size_t)BATCH*TK;
    for (int i = tid; i < TK; i += 1024) {
        float a = sc[i] * inv2;
        attn_out[boff + i] = a;
        float nc = coverage[boff + i] + a;
        ncov_out[boff + i] = fminf(fmaxf(nc, 0.f), 1.f);
    }
}

// ---------------- kernel 4: context partials c_t_part[b,ch,h] ----------------
__global__ void __launch_bounds__(256)
ctx_kernel(const float* __restrict__ enc, const float* __restrict__ attn)
{
    const int b = blockIdx.y, ch = blockIdx.x;
    __shared__ float sa[256];
    const int h = threadIdx.x;
    const size_t base = (size_t)b*TK + (size_t)ch*256;
    sa[h] = attn[base + h];
    __syncthreads();
    const float* e = enc + base*H + h;
    float a0 = 0.f, a1 = 0.f, a2 = 0.f, a3 = 0.f;
    #pragma unroll 4
    for (int t = 0; t < 256; t += 4) {
        a0 = fmaf(sa[t],   e[(size_t)t*H],       a0);
        a1 = fmaf(sa[t+1], e[(size_t)(t+1)*H],   a1);
        a2 = fmaf(sa[t+2], e[(size_t)(t+2)*H],   a2);
        a3 = fmaf(sa[t+3], e[(size_t)(t+3)*H],   a3);
    }
    g_ct_part[((size_t)b*32 + ch)*H + h] = (a0 + a1) + (a2 + a3);
}

// ---------------- kernel 5: combine partials -> c_t ----------------
__global__ void __launch_bounds__(256)
ct_combine(float* __restrict__ out)
{
    const int b = blockIdx.x, h = threadIdx.x;
    float acc = 0.f;
    #pragma unroll
    for (int ch = 0; ch < 32; ch++)
        acc += g_ct_part[((size_t)b*32 + ch)*H + h];
    out[(size_t)b*H + h] = acc;
}

// ---------------- launch ----------------
extern "C" void kernel_launch(void* const* d_in, const int* in_sizes, int n_in,
                              void* d_out, int out_size)
{
    const float* s_t_hat = (const float*)d_in[0];
    const float* enc     = (const float*)d_in[1];
    const float* mask    = (const float*)d_in[2];
    const float* cov     = (const float*)d_in[3];
    // d_in[4] = attn_dist_node_to_token : unused by reference
    const float* We      = (const float*)d_in[5];
    const float* Wd      = (const float*)d_in[6];
    const float* bd      = (const float*)d_in[7];
    const float* wc      = (const float*)d_in[8];
    const float* v       = (const float*)d_in[9];
    float* out = (float*)d_out;

    const int SMEM_B = (256*WSTR + 2*TM*XSTR)*4 + (4*TM + 3*GH)*4;  // 179712 B
    cudaFuncSetAttribute(scores_kernel, cudaFuncAttributeMaxDynamicSharedMemorySize, SMEM_B);

    dec_proj_kernel<<<BATCH, 256>>>(s_t_hat, Wd, bd);
    scores_kernel<<<296, NTHREADS, SMEM_B>>>(enc, cov, We, wc, v);
    softmax_kernel<<<BATCH, 1024>>>(mask, cov, out);
    dim3 gctx(32, BATCH);
    ctx_kernel<<<gctx, 256>>>(enc, out + BATCH*H);
    ct_combine<<<BATCH, 256>>>(out);
}

// round 3
// speedup vs baseline: 2.2185x; 2.2185x over previous
#include <cuda_runtime.h>
#include <cuda_fp16.h>
#include <math.h>
#include <stdint.h>

#define BATCH 32
#define TK    8192
#define H     256
#define NROWS (BATCH*TK)     // 262144
#define TM    128
#define NT    (NROWS/TM)     // 2048
#define NTHREADS 512

// scores SMEM layout (bytes)
#define SM_X   0              // 2 x 65536 (128 rows x 256 k fp16, swizzled)
#define SM_W   131072         // 65536 (128 g x 256 k fp16, swizzled)
#define SM_DEC 196608         // 16384 (32 batches x 128 g fp32)
#define SM_WC  212992         // 512
#define SM_V   213504         // 512
#define SM_SP  214016         // 2048 (4 cw x 128 rows fp32)
#define SMEM_TOTAL 216064

// ---------------- device scratch ----------------
__device__ __half g_enc_h[(size_t)NROWS * H];   // fp16 copy of encoder_outputs
__device__ float  g_dec_fea[BATCH*H];
__device__ float  g_scores[2][NROWS];
__device__ float  g_ct_part[BATCH*32*H];

// ---------------- helpers ----------------
__device__ __forceinline__ uint32_t smem_u32(const void* p) {
    uint32_t a;
    asm("{ .reg .u64 t; cvta.to.shared.u64 t, %1; cvt.u32.u64 %0, t; }" : "=r"(a) : "l"(p));
    return a;
}
__device__ __forceinline__ float fast_tanh(float x) {
    float r; asm("tanh.approx.f32 %0, %1;" : "=f"(r) : "f"(x)); return r;
}
__device__ __forceinline__ uint32_t f2h2(float a, float b) {
    __half2 h = __floats2half2_rn(a, b);
    return *reinterpret_cast<uint32_t*>(&h);
}
__device__ __forceinline__ void ldsm4(uint32_t* r, uint32_t addr) {
    asm volatile("ldmatrix.sync.aligned.m8n8.x4.shared.b16 {%0,%1,%2,%3}, [%4];"
        : "=r"(r[0]), "=r"(r[1]), "=r"(r[2]), "=r"(r[3]) : "r"(addr));
}
__device__ __forceinline__ void mma16816(float* c, const uint32_t* a, uint32_t b0, uint32_t b1) {
    asm volatile(
        "mma.sync.aligned.m16n8k16.row.col.f32.f16.f16.f32 "
        "{%0,%1,%2,%3}, {%4,%5,%6,%7}, {%8,%9}, {%0,%1,%2,%3};"
        : "+f"(c[0]), "+f"(c[1]), "+f"(c[2]), "+f"(c[3])
        : "r"(a[0]), "r"(a[1]), "r"(a[2]), "r"(a[3]), "r"(b0), "r"(b1));
}
#define CP_ASYNC16(dst, src) \
    asm volatile("cp.async.cg.shared.global [%0], [%1], 16;" :: "r"(dst), "l"(src) : "memory")
#define CP_COMMIT() asm volatile("cp.async.commit_group;" ::: "memory")
#define CP_WAIT1()  asm volatile("cp.async.wait_group 1;" ::: "memory")

// ---------------- kernel 0: enc fp32 -> fp16 ----------------
__global__ void __launch_bounds__(512)
cvt_kernel(const float* __restrict__ enc)
{
    size_t u = (size_t)blockIdx.x * 512 + threadIdx.x;   // 8 halves per thread
    const float4* s = (const float4*)enc + u*2;
    float4 a = __ldg(s), b = __ldg(s + 1);
    uint4 o;
    o.x = f2h2(a.x, a.y); o.y = f2h2(a.z, a.w);
    o.z = f2h2(b.x, b.y); o.w = f2h2(b.z, b.w);
    *reinterpret_cast<uint4*>(g_enc_h + u*8) = o;
}

// ---------------- kernel 1: dec_fea ----------------
__global__ void __launch_bounds__(256)
dec_proj_kernel(const float* __restrict__ s_t_hat, const float* __restrict__ Wd,
                const float* __restrict__ bd)
{
    __shared__ float s[512];
    int b = blockIdx.x;
    for (int i = threadIdx.x; i < 512; i += 256) s[i] = s_t_hat[b*512 + i];
    __syncthreads();
    int warp = threadIdx.x >> 5, lane = threadIdx.x & 31;
    for (int g = warp*32; g < warp*32 + 32; g++) {
        const float* w = Wd + (size_t)g*512;
        float acc = 0.f;
        #pragma unroll 4
        for (int j = lane; j < 512; j += 32) acc += s[j]*w[j];
        #pragma unroll
        for (int o = 16; o; o >>= 1) acc += __shfl_xor_sync(0xffffffffu, acc, o);
        if (lane == 0) g_dec_fea[b*H + g] = acc + bd[g];
    }
}

// ---------------- kernel 2: fused GEMM(fp16 mma) + tanh + v-dot ----------------
__device__ __forceinline__ void load_tile_async(uint32_t xdst, int row0, int tid)
{
    #pragma unroll
    for (int j = 0; j < 8; j++) {
        int idx = tid + j*NTHREADS;
        int r = idx >> 5, c = idx & 31;
        uint32_t dst = xdst + r*512 + (((c ^ (r & 7))) << 4);
        const __half* src = g_enc_h + (size_t)(row0 + r)*H + c*8;
        CP_ASYNC16(dst, src);
    }
}

__global__ void __launch_bounds__(NTHREADS, 1)
scores_kernel(const float* __restrict__ We, const float* __restrict__ coverage,
              const float* __restrict__ wc, const float* __restrict__ v)
{
    extern __shared__ char smem_c[];
    const uint32_t sb = smem_u32(smem_c);
    const int tid   = threadIdx.x;
    const int gh    = blockIdx.x & 1;
    const int tile0 = blockIdx.x >> 1;

    // ---- stage W half: fp32 -> fp16, swizzled ----
    #pragma unroll
    for (int j = 0; j < 8; j++) {
        int idx = tid + j*NTHREADS;        // 4096 units of 8 k-values
        int g = idx >> 5, c = idx & 31;
        const float4* s = (const float4*)(We + (size_t)(gh*128 + g)*H + c*8);
        float4 x = __ldg(s), y = __ldg(s + 1);
        uint4 o;
        o.x = f2h2(x.x, x.y); o.y = f2h2(x.z, x.w);
        o.z = f2h2(y.x, y.y); o.w = f2h2(y.z, y.w);
        *reinterpret_cast<uint4*>(smem_c + SM_W + g*512 + ((c ^ (g & 7)) << 4)) = o;
    }
    if (tid < 128) {
        ((float*)(smem_c + SM_WC))[tid] = wc[gh*128 + tid];
        ((float*)(smem_c + SM_V ))[tid] = v [gh*128 + tid];
    }
    for (int i = tid; i < 32*128; i += NTHREADS)
        ((float*)(smem_c + SM_DEC))[i] = g_dec_fea[(i >> 7)*H + gh*128 + (i & 127)];

    // ---- fragment geometry ----
    const int lane = tid & 31, warp = tid >> 5;
    const int rw = warp >> 2, cw = warp & 3;            // 4 row-warps x 4 col-warps
    const int arow = rw*32 + (lane & 15);
    const int brow = cw*32 + ((lane >> 4) << 3) + (lane & 7);
    const int sw   = lane & 7;
    const int aCb  = lane >> 4;          // 0/1
    const int bCb  = (lane >> 3) & 1;    // 0/1
    const uint32_t bRow = sb + SM_W + brow*512;
    const int lq = lane >> 2, lr = lane & 3;
    const float2* wc2  = (const float2*)(smem_c + SM_WC);
    const float2* v2p  = (const float2*)(smem_c + SM_V);
    float* sPart = (float*)(smem_c + SM_SP);

    // ---- prologue: prefetch first tile ----
    load_tile_async(sb + SM_X, tile0*TM, tid);
    CP_COMMIT();

    int it = 0;
    for (int tile = tile0; tile < NT; tile += 148, it++) {
        const int buf  = it & 1;
        const int row0 = tile * TM;

        int ntile = tile + 148;
        if (ntile < NT) load_tile_async(sb + SM_X + (buf ^ 1)*65536, ntile*TM, tid);
        CP_COMMIT();
        CP_WAIT1();
        __syncthreads();

        // ---- mainloop: 128x128x256 fp16 MMA ----
        float acc[2][4][4];
        #pragma unroll
        for (int m = 0; m < 2; m++)
            #pragma unroll
            for (int n = 0; n < 4; n++)
                #pragma unroll
                for (int q = 0; q < 4; q++) acc[m][n][q] = 0.f;

        const uint32_t aRow = sb + SM_X + buf*65536 + arow*512;
        #pragma unroll 4
        for (int ks = 0; ks < 16; ks++) {
            uint32_t aA = aRow + (((ks*2 + aCb) ^ sw) << 4);
            uint32_t bA = bRow + (((ks*2 + bCb) ^ sw) << 4);
            uint32_t a0[4], a1[4], b0[4], b1[4];
            ldsm4(a0, aA);
            ldsm4(a1, aA + 8192);       // rows +16
            ldsm4(b0, bA);
            ldsm4(b1, bA + 8192);       // cols +16
            mma16816(acc[0][0], a0, b0[0], b0[1]);
            mma16816(acc[0][1], a0, b0[2], b0[3]);
            mma16816(acc[0][2], a0, b1[0], b1[1]);
            mma16816(acc[0][3], a0, b1[2], b1[3]);
            mma16816(acc[1][0], a1, b0[0], b0[1]);
            mma16816(acc[1][1], a1, b0[2], b0[3]);
            mma16816(acc[1][2], a1, b1[0], b1[1]);
            mma16816(acc[1][3], a1, b1[2], b1[3]);
        }

        // ---- epilogue ----
        const int b = row0 >> 13;
        const float2* dec2 = (const float2*)(smem_c + SM_DEC) + b*64;
        const int rbase = rw*32 + lq;
        float cov0 = coverage[row0 + rbase];
        float cov1 = coverage[row0 + rbase + 8];
        float cov2 = coverage[row0 + rbase + 16];
        float cov3 = coverage[row0 + rbase + 24];
        float rowsum[4] = {0.f, 0.f, 0.f, 0.f};
        #pragma unroll
        for (int m = 0; m < 2; m++) {
            const float covA = m ? cov2 : cov0;
            const float covB = m ? cov3 : cov1;
            #pragma unroll
            for (int nt_ = 0; nt_ < 4; nt_++) {
                const int i2 = cw*16 + nt_*4 + lr;
                float2 w2 = wc2[i2], d2 = dec2[i2], vv = v2p[i2];
                rowsum[m*2]   += vv.x*fast_tanh(acc[m][nt_][0] + d2.x + covA*w2.x)
                               + vv.y*fast_tanh(acc[m][nt_][1] + d2.y + covA*w2.y);
                rowsum[m*2+1] += vv.x*fast_tanh(acc[m][nt_][2] + d2.x + covB*w2.x)
                               + vv.y*fast_tanh(acc[m][nt_][3] + d2.y + covB*w2.y);
            }
        }
        #pragma unroll
        for (int o = 1; o < 4; o <<= 1)
            #pragma unroll
            for (int q = 0; q < 4; q++)
                rowsum[q] += __shfl_xor_sync(0xffffffffu, rowsum[q], o);
        if (lr == 0) {
            #pragma unroll
            for (int m = 0; m < 2; m++) {
                sPart[cw*TM + rw*32 + m*16 + lq]     = rowsum[m*2];
                sPart[cw*TM + rw*32 + m*16 + 8 + lq] = rowsum[m*2+1];
            }
        }
        __syncthreads();
        if (tid < TM) {
            float s = sPart[tid] + sPart[TM+tid] + sPart[2*TM+tid] + sPart[3*TM+tid];
            g_scores[gh][row0 + tid] = s;
        }
        __syncthreads();   // protects buf reuse + sPart
    }
}

// ---------------- kernel 3: softmax (mask folded) + new_cov ----------------
__global__ void __launch_bounds__(1024)
softmax_kernel(const float* __restrict__ mask, const float* __restrict__ coverage,
               float* __restrict__ out)
{
    __shared__ float sc[TK];
    __shared__ float red[32];
    const int b = blockIdx.x, tid = threadIdx.x;
    const int lane = tid & 31, warp = tid >> 5;
    const size_t boff = (size_t)b * TK;

    float lmax = -3.4e38f;
    for (int i = tid; i < TK; i += 1024) {
        float s = g_scores[0][boff + i] + g_scores[1][boff + i];
        sc[i] = s;
        lmax = fmaxf(lmax, s);
    }
    #pragma unroll
    for (int o = 16; o; o >>= 1) lmax = fmaxf(lmax, __shfl_xor_sync(~0u, lmax, o));
    if (lane == 0) red[warp] = lmax;
    __syncthreads();
    float M = red[lane];
    #pragma unroll
    for (int o = 16; o; o >>= 1) M = fmaxf(M, __shfl_xor_sync(~0u, M, o));
    __syncthreads();

    float lsum = 0.f;
    for (int i = tid; i < TK; i += 1024) {
        float t = __expf(sc[i] - M) * mask[boff + i];
        sc[i] = t;
        lsum += t;
    }
    #pragma unroll
    for (int o = 16; o; o >>= 1) lsum += __shfl_xor_sync(~0u, lsum, o);
    if (lane == 0) red[warp] = lsum;
    __syncthreads();
    float S = red[lane];
    #pragma unroll
    for (int o = 16; o; o >>= 1) S += __shfl_xor_sync(~0u, S, o);

    const float invS = 1.f / S;
    float* attn_out = out + BATCH*H;
    float* ncov_out = attn_out + (size_t)BATCH*TK;
    for (int i = tid; i < TK; i += 1024) {
        float a = sc[i] * invS;
        attn_out[boff + i] = a;
        float nc = coverage[boff + i] + a;
        ncov_out[boff + i] = fminf(fmaxf(nc, 0.f), 1.f);
    }
}

// ---------------- kernel 4: context partials (fp16 enc) ----------------
__global__ void __launch_bounds__(128)
ctx_kernel(const float* __restrict__ attn)
{
    const int b = blockIdx.y, ch = blockIdx.x;
    __shared__ float sa[256];
    const int t = threadIdx.x;           // h2 index 0..127
    const size_t base = (size_t)b*TK + (size_t)ch*256;
    sa[t]       = attn[base + t];
    sa[t + 128] = attn[base + t + 128];
    __syncthreads();
    const __half2* e = (const __half2*)g_enc_h + base*(H/2) + t;
    float ax0 = 0.f, ay0 = 0.f, ax1 = 0.f, ay1 = 0.f;
    #pragma unroll 8
    for (int k = 0; k < 256; k += 2) {
        float2 f0 = __half22float2(e[(size_t)k*(H/2)]);
        float2 f1 = __half22float2(e[(size_t)(k+1)*(H/2)]);
        ax0 = fmaf(sa[k],   f0.x, ax0);  ay0 = fmaf(sa[k],   f0.y, ay0);
        ax1 = fmaf(sa[k+1], f1.x, ax1);  ay1 = fmaf(sa[k+1], f1.y, ay1);
    }
    float* dst = g_ct_part + ((size_t)b*32 + ch)*H + 2*t;
    dst[0] = ax0 + ax1;
    dst[1] = ay0 + ay1;
}

// ---------------- kernel 5: combine ----------------
__global__ void __launch_bounds__(256)
ct_combine(float* __restrict__ out)
{
    const int b = blockIdx.x, h = threadIdx.x;
    float acc = 0.f;
    #pragma unroll
    for (int ch = 0; ch < 32; ch++)
        acc += g_ct_part[((size_t)b*32 + ch)*H + h];
    out[(size_t)b*H + h] = acc;
}

// ---------------- launch ----------------
extern "C" void kernel_launch(void* const* d_in, const int* in_sizes, int n_in,
                              void* d_out, int out_size)
{
    const float* s_t_hat = (const float*)d_in[0];
    const float* enc     = (const float*)d_in[1];
    const float* mask    = (const float*)d_in[2];
    const float* cov     = (const float*)d_in[3];
    const float* We      = (const float*)d_in[5];
    const float* Wd      = (const float*)d_in[6];
    const float* bd      = (const float*)d_in[7];
    const float* wc      = (const float*)d_in[8];
    const float* v       = (const float*)d_in[9];
    float* out = (float*)d_out;

    cudaFuncSetAttribute(scores_kernel, cudaFuncAttributeMaxDynamicSharedMemorySize, SMEM_TOTAL);

    cvt_kernel<<<16384, 512>>>(enc);                 // 64M halves / (512*8)
    dec_proj_kernel<<<BATCH, 256>>>(s_t_hat, Wd, bd);
    scores_kernel<<<296, NTHREADS, SMEM_TOTAL>>>(We, cov, wc, v);
    softmax_kernel<<<BATCH, 1024>>>(mask, cov, out);
    dim3 gctx(32, BATCH);
    ctx_kernel<<<gctx, 128>>>(out + BATCH*H);
    ct_combine<<<BATCH, 256>>>(out);
}

// round 4
// speedup vs baseline: 2.3460x; 1.0575x over previous
#include <cuda_runtime.h>
#include <cuda_fp16.h>
#include <math.h>
#include <stdint.h>

#define BATCH 32
#define TK    8192
#define H     256
#define NROWS (BATCH*TK)     // 262144
#define TM    64
#define NT    (NROWS/TM)     // 4096
#define NTHREADS 512

// scores SMEM layout (bytes)
#define SM_X   0              // 2 x 32768 (64 rows x 256 k fp16, swizzled)
#define SM_W   65536          // 131072 (256 g x 256 k fp16, swizzled)
#define SM_WC  196608         // 1024
#define SM_V   197632         // 1024
#define SM_SP  198656         // 2048 (8 cw x 64 rows fp32)
#define SMEM_TOTAL 200704

// ---------------- device scratch ----------------
__device__ __half g_enc_h[(size_t)NROWS * H];   // fp16 copy (written by scores, read by ctx)
__device__ float  g_dec_fea[BATCH*H];
__device__ float  g_scores[NROWS];
__device__ float  g_ct_part[BATCH*32*H];

// ---------------- helpers ----------------
__device__ __forceinline__ uint32_t smem_u32(const void* p) {
    uint32_t a;
    asm("{ .reg .u64 t; cvta.to.shared.u64 t, %1; cvt.u32.u64 %0, t; }" : "=r"(a) : "l"(p));
    return a;
}
__device__ __forceinline__ float fast_tanh(float x) {
    float r; asm("tanh.approx.f32 %0, %1;" : "=f"(r) : "f"(x)); return r;
}
__device__ __forceinline__ uint32_t f2h2(float a, float b) {
    __half2 h = __floats2half2_rn(a, b);
    return *reinterpret_cast<uint32_t*>(&h);
}
__device__ __forceinline__ void ldsm4(uint32_t* r, uint32_t addr) {
    asm volatile("ldmatrix.sync.aligned.m8n8.x4.shared.b16 {%0,%1,%2,%3}, [%4];"
        : "=r"(r[0]), "=r"(r[1]), "=r"(r[2]), "=r"(r[3]) : "r"(addr));
}
__device__ __forceinline__ void mma16816(float* c, const uint32_t* a, uint32_t b0, uint32_t b1) {
    asm volatile(
        "mma.sync.aligned.m16n8k16.row.col.f32.f16.f16.f32 "
        "{%0,%1,%2,%3}, {%4,%5,%6,%7}, {%8,%9}, {%0,%1,%2,%3};"
        : "+f"(c[0]), "+f"(c[1]), "+f"(c[2]), "+f"(c[3])
        : "r"(a[0]), "r"(a[1]), "r"(a[2]), "r"(a[3]), "r"(b0), "r"(b1));
}

// ---------------- kernel 1: dec_fea ----------------
__global__ void __launch_bounds__(256)
dec_proj_kernel(const float* __restrict__ s_t_hat, const float* __restrict__ Wd,
                const float* __restrict__ bd)
{
    __shared__ float s[512];
    int b = blockIdx.x;
    for (int i = threadIdx.x; i < 512; i += 256) s[i] = s_t_hat[b*512 + i];
    __syncthreads();
    int warp = threadIdx.x >> 5, lane = threadIdx.x & 31;
    for (int g = warp*32; g < warp*32 + 32; g++) {
        const float* w = Wd + (size_t)g*512;
        float acc = 0.f;
        #pragma unroll 4
        for (int j = lane; j < 512; j += 32) acc += s[j]*w[j];
        #pragma unroll
        for (int o = 16; o; o >>= 1) acc += __shfl_xor_sync(0xffffffffu, acc, o);
        if (lane == 0) g_dec_fea[b*H + g] = acc + bd[g];
    }
}

// ---------------- kernel 2: fused GEMM(N=256) + tanh + v-dot + fp16 copy ----------------
__global__ void __launch_bounds__(NTHREADS, 1)
scores_kernel(const float* __restrict__ enc, const float* __restrict__ We,
              const float* __restrict__ coverage, const float* __restrict__ wc,
              const float* __restrict__ v)
{
    extern __shared__ char smem_c[];
    const uint32_t sb = smem_u32(smem_c);
    const int tid   = threadIdx.x;
    const int tile0 = blockIdx.x;

    // ---- stage full W (256 g x 256 k), fp32 -> fp16, swizzled ----
    #pragma unroll
    for (int j = 0; j < 16; j++) {
        int idx = tid + j*NTHREADS;        // 8192 units of 8 k-values
        int g = idx >> 5, c = idx & 31;
        const float4* s = (const float4*)(We + (size_t)g*H + c*8);
        float4 x = __ldg(s), y = __ldg(s + 1);
        uint4 o;
        o.x = f2h2(x.x, x.y); o.y = f2h2(x.z, x.w);
        o.z = f2h2(y.x, y.y); o.w = f2h2(y.z, y.w);
        *reinterpret_cast<uint4*>(smem_c + SM_W + g*512 + ((c ^ (g & 7)) << 4)) = o;
    }
    if (tid < 256) {
        ((float*)(smem_c + SM_WC))[tid] = wc[tid];
        ((float*)(smem_c + SM_V ))[tid] = v[tid];
    }

    // ---- prologue: stage tile0 (fp32 load -> cvt -> STS + STG fp16 copy) ----
    {
        const int row0 = tile0 * TM;
        #pragma unroll
        for (int j = 0; j < 8; j++) {
            int idx = tid + j*NTHREADS;         // 4096 units of 4 floats
            int r = idx >> 6, c = idx & 63;
            float4 x = __ldg((const float4*)(enc + (size_t)(row0 + r)*H + c*4));
            uint2 o; o.x = f2h2(x.x, x.y); o.y = f2h2(x.z, x.w);
            *(uint2*)(smem_c + SM_X + r*512 + ((((c>>1) ^ (r & 7))) << 4) + (c & 1)*8) = o;
            *(uint2*)((char*)g_enc_h + ((size_t)(row0 + r)*H + c*4)*2) = o;
        }
    }

    // ---- fragment geometry: 16 warps = 2 row-warps x 8 col-warps ----
    const int lane = tid & 31, warp = tid >> 5;
    const int rw = warp >> 3, cw = warp & 7;
    const int sw = lane & 7;
    const int arow = rw*32 + (lane & 15);
    const int brow = cw*32 + ((lane >> 4) << 3) + (lane & 7);
    const int aCb  = lane >> 4;
    const int bCb  = (lane >> 3) & 1;
    const uint32_t aBase0 = sb + SM_X + arow*512;
    const uint32_t bBase  = sb + SM_W + brow*512;
    const int lq = lane >> 2, lr = lane & 3;
    const float2* wc2 = (const float2*)(smem_c + SM_WC);
    const float2* v2p = (const float2*)(smem_c + SM_V);
    float* sPart = (float*)(smem_c + SM_SP);

    int it = 0;
    for (int tile = tile0; tile < NT; tile += 148, it++) {
        const int buf  = it & 1;
        const int row0 = tile * TM;
        __syncthreads();   // staged buf + W visible; sPart free

        // prefetch next tile's fp32 into registers (latency hidden by MMA)
        const int ntile = tile + 148;
        const bool hasnext = ntile < NT;
        float4 stg[8];
        if (hasnext) {
            const int nrow0 = ntile * TM;
            #pragma unroll
            for (int j = 0; j < 8; j++) {
                int idx = tid + j*NTHREADS;
                int r = idx >> 6, c = idx & 63;
                stg[j] = __ldg((const float4*)(enc + (size_t)(nrow0 + r)*H + c*4));
            }
        }

        // ---- mainloop: 64x256x256 fp16 MMA ----
        float acc[2][4][4];
        #pragma unroll
        for (int m = 0; m < 2; m++)
            #pragma unroll
            for (int n = 0; n < 4; n++)
                #pragma unroll
                for (int q = 0; q < 4; q++) acc[m][n][q] = 0.f;

        const uint32_t aBase = aBase0 + buf*32768;
        #pragma unroll
        for (int ks = 0; ks < 16; ks++) {
            uint32_t aA = aBase + (((ks*2 + aCb) ^ sw) << 4);
            uint32_t bA = bBase + (((ks*2 + bCb) ^ sw) << 4);
            uint32_t a0[4], a1[4], b0[4], b1[4];
            ldsm4(a0, aA);
            ldsm4(a1, aA + 8192);       // rows +16
            ldsm4(b0, bA);
            ldsm4(b1, bA + 8192);       // cols +16
            mma16816(acc[0][0], a0, b0[0], b0[1]);
            mma16816(acc[0][1], a0, b0[2], b0[3]);
            mma16816(acc[0][2], a0, b1[0], b1[1]);
            mma16816(acc[0][3], a0, b1[2], b1[3]);
            mma16816(acc[1][0], a1, b0[0], b0[1]);
            mma16816(acc[1][1], a1, b0[2], b0[3]);
            mma16816(acc[1][2], a1, b1[0], b1[1]);
            mma16816(acc[1][3], a1, b1[2], b1[3]);
        }

        // ---- epilogue ----
        const int b = row0 >> 13;
        const float cov0 = coverage[row0 + rw*32 + lq];
        const float cov1 = coverage[row0 + rw*32 + lq + 8];
        const float cov2 = coverage[row0 + rw*32 + lq + 16];
        const float cov3 = coverage[row0 + rw*32 + lq + 24];
        float rowsum[4] = {0.f, 0.f, 0.f, 0.f};
        #pragma unroll
        for (int n = 0; n < 4; n++) {
            const int i2 = cw*16 + n*4 + lr;
            float2 w2 = wc2[i2], vv = v2p[i2];
            float2 d2 = __ldg((const float2*)g_dec_fea + b*128 + i2);
            rowsum[0] += vv.x*fast_tanh(acc[0][n][0] + d2.x + cov0*w2.x)
                       + vv.y*fast_tanh(acc[0][n][1] + d2.y + cov0*w2.y);
            rowsum[1] += vv.x*fast_tanh(acc[0][n][2] + d2.x + cov1*w2.x)
                       + vv.y*fast_tanh(acc[0][n][3] + d2.y + cov1*w2.y);
            rowsum[2] += vv.x*fast_tanh(acc[1][n][0] + d2.x + cov2*w2.x)
                       + vv.y*fast_tanh(acc[1][n][1] + d2.y + cov2*w2.y);
            rowsum[3] += vv.x*fast_tanh(acc[1][n][2] + d2.x + cov3*w2.x)
                       + vv.y*fast_tanh(acc[1][n][3] + d2.y + cov3*w2.y);
        }
        #pragma unroll
        for (int o = 1; o < 4; o <<= 1)
            #pragma unroll
            for (int q = 0; q < 4; q++)
                rowsum[q] += __shfl_xor_sync(0xffffffffu, rowsum[q], o);
        if (lr == 0) {
            sPart[cw*64 + rw*32 + lq]      = rowsum[0];
            sPart[cw*64 + rw*32 + lq + 8]  = rowsum[1];
            sPart[cw*64 + rw*32 + lq + 16] = rowsum[2];
            sPart[cw*64 + rw*32 + lq + 24] = rowsum[3];
        }
        __syncthreads();
        if (tid < TM) {
            float s = 0.f;
            #pragma unroll
            for (int k = 0; k < 8; k++) s += sPart[k*64 + tid];
            g_scores[row0 + tid] = s;
        }

        // ---- stage next tile into buf^1 (visible after next loop-top sync) ----
        if (hasnext) {
            const int nrow0 = ntile * TM;
            char* dst = smem_c + SM_X + (buf ^ 1)*32768;
            #pragma unroll
            for (int j = 0; j < 8; j++) {
                int idx = tid + j*NTHREADS;
                int r = idx >> 6, c = idx & 63;
                uint2 o; o.x = f2h2(stg[j].x, stg[j].y); o.y = f2h2(stg[j].z, stg[j].w);
                *(uint2*)(dst + r*512 + ((((c>>1) ^ (r & 7))) << 4) + (c & 1)*8) = o;
                *(uint2*)((char*)g_enc_h + ((size_t)(nrow0 + r)*H + c*4)*2) = o;
            }
        }
    }
}

// ---------------- kernel 3: online softmax (mask folded) + new_cov ----------------
__global__ void __launch_bounds__(1024)
softmax_kernel(const float* __restrict__ mask, const float* __restrict__ coverage,
               float* __restrict__ out)
{
    __shared__ float2 red[32];
    const int b = blockIdx.x, tid = threadIdx.x;
    const int lane = tid & 31, warp = tid >> 5;
    const size_t boff = (size_t)b * TK;

    float sv[8], mk[8];
    float m_t = -3.4e38f;
    #pragma unroll
    for (int j = 0; j < 8; j++) {
        int i = tid + j*1024;
        sv[j] = g_scores[boff + i];
        mk[j] = mask[boff + i];
        m_t = fmaxf(m_t, sv[j]);
    }
    float s_t = 0.f;
    #pragma unroll
    for (int j = 0; j < 8; j++) s_t += __expf(sv[j] - m_t) * mk[j];

    #pragma unroll
    for (int o = 16; o; o >>= 1) {
        float m2 = __shfl_xor_sync(~0u, m_t, o);
        float s2 = __shfl_xor_sync(~0u, s_t, o);
        float mn = fmaxf(m_t, m2);
        s_t = s_t * __expf(m_t - mn) + s2 * __expf(m2 - mn);
        m_t = mn;
    }
    if (lane == 0) red[warp] = make_float2(m_t, s_t);
    __syncthreads();
    float2 r = red[lane];
    float M = r.x, S = r.y;
    #pragma unroll
    for (int o = 16; o; o >>= 1) {
        float m2 = __shfl_xor_sync(~0u, M, o);
        float s2 = __shfl_xor_sync(~0u, S, o);
        float mn = fmaxf(M, m2);
        S = S * __expf(M - mn) + s2 * __expf(m2 - mn);
        M = mn;
    }
    M = __shfl_sync(~0u, M, 0);
    S = __shfl_sync(~0u, S, 0);
    if (warp == 0 && lane == 0) red[0] = make_float2(M, S);
    __syncthreads();
    M = red[0].x; S = red[0].y;

    const float invS = 1.f / S;
    float* attn_out = out + BATCH*H;
    float* ncov_out = attn_out + (size_t)BATCH*TK;
    #pragma unroll
    for (int j = 0; j < 8; j++) {
        int i = tid + j*1024;
        float a = __expf(sv[j] - M) * mk[j] * invS;
        attn_out[boff + i] = a;
        float nc = coverage[boff + i] + a;
        ncov_out[boff + i] = fminf(fmaxf(nc, 0.f), 1.f);
    }
}

// ---------------- kernel 4: context partials (fp16 enc copy) ----------------
__global__ void __launch_bounds__(128)
ctx_kernel(const float* __restrict__ attn)
{
    const int b = blockIdx.y, ch = blockIdx.x;
    __shared__ float sa[256];
    const int t = threadIdx.x;           // h2 index 0..127
    const size_t base = (size_t)b*TK + (size_t)ch*256;
    sa[t]       = attn[base + t];
    sa[t + 128] = attn[base + t + 128];
    __syncthreads();
    const __half2* e = (const __half2*)g_enc_h + base*(H/2) + t;
    float ax0 = 0.f, ay0 = 0.f, ax1 = 0.f, ay1 = 0.f;
    #pragma unroll 8
    for (int k = 0; k < 256; k += 2) {
        float2 f0 = __half22float2(e[(size_t)k*(H/2)]);
        float2 f1 = __half22float2(e[(size_t)(k+1)*(H/2)]);
        ax0 = fmaf(sa[k],   f0.x, ax0);  ay0 = fmaf(sa[k],   f0.y, ay0);
        ax1 = fmaf(sa[k+1], f1.x, ax1);  ay1 = fmaf(sa[k+1], f1.y, ay1);
    }
    float* dst = g_ct_part + ((size_t)b*32 + ch)*H + 2*t;
    dst[0] = ax0 + ax1;
    dst[1] = ay0 + ay1;
}

// ---------------- kernel 5: combine ----------------
__global__ void __launch_bounds__(256)
ct_combine(float* __restrict__ out)
{
    const int b = blockIdx.x, h = threadIdx.x;
    float acc = 0.f;
    #pragma unroll
    for (int ch = 0; ch < 32; ch++)
        acc += g_ct_part[((size_t)b*32 + ch)*H + h];
    out[(size_t)b*H + h] = acc;
}

// ---------------- launch ----------------
extern "C" void kernel_launch(void* const* d_in, const int* in_sizes, int n_in,
                              void* d_out, int out_size)
{
    const float* s_t_hat = (const float*)d_in[0];
    const float* enc     = (const float*)d_in[1];
    const float* mask    = (const float*)d_in[2];
    const float* cov     = (const float*)d_in[3];
    const float* We      = (const float*)d_in[5];
    const float* Wd      = (const float*)d_in[6];
    const float* bd      = (const float*)d_in[7];
    const float* wc      = (const float*)d_in[8];
    const float* v       = (const float*)d_in[9];
    float* out = (float*)d_out;

    cudaFuncSetAttribute(scores_kernel, cudaFuncAttributeMaxDynamicSharedMemorySize, SMEM_TOTAL);

    dec_proj_kernel<<<BATCH, 256>>>(s_t_hat, Wd, bd);
    scores_kernel<<<148, NTHREADS, SMEM_TOTAL>>>(enc, We, cov, wc, v);
    softmax_kernel<<<BATCH, 1024>>>(mask, cov, out);
    dim3 gctx(32, BATCH);
    ctx_kernel<<<gctx, 128>>>(out + BATCH*H);
    ct_combine<<<BATCH, 256>>>(out);
}